// round 1
// baseline (speedup 1.0000x reference)
#include <cuda_runtime.h>
#include <math.h>

// Problem constants
#define BT    2048      // B*T = 4*512
#define NB    24        // bands
#define D     512       // DIM
#define E2    1024      // 2*DIM
#define OUTW  2016      // sum(DIM_INPUTS)
#define W1C   4032      // 2*OUTW

// Scratch for stage-1 output h: [BT][NB][D] fp32 = 96 MB (static device global,
// allowed under the allocation guards).
__device__ float g_h[(size_t)BT * NB * D];

__device__ __forceinline__ float glu(float a, float g) {
    return tanhf(a) * (1.0f / (1.0f + __expf(-g)));
}

// ---------------------------------------------------------------------------
// Stage 1: z = x[:, :, n, :] @ W0[n] + b0[n];  h = tanh(z_a) * sigmoid(z_g)
// Grid: (BT/128, 512/64 a-cols, 24 bands). Block 256 threads.
// Tile: M=128 rows, 64 a-cols + their 64 matching gate-cols (GEMM N=128), K=512.
// Thread (tx,ty) in 16x16: 8 rows x (4 a-cols + 4 gate-cols) => 8x8 accumulators.
// ---------------------------------------------------------------------------
__global__ __launch_bounds__(256) void stage1_kernel(
    const float* __restrict__ x, const float* __restrict__ W0,
    const float* __restrict__ b0)
{
    const int row0 = blockIdx.x * 128;
    const int ja   = blockIdx.y * 64;
    const int n    = blockIdx.z;

    __shared__ __align__(16) float As[16][128];   // As[k][m]
    __shared__ __align__(16) float Bs[16][128];   // [k][c]: c<64 a-cols, c>=64 gate-cols

    const int tid = threadIdx.x;
    const int tx  = tid & 15;
    const int ty  = tid >> 4;

    float acc[8][8];
    #pragma unroll
    for (int i = 0; i < 8; i++)
        #pragma unroll
        for (int j = 0; j < 8; j++) acc[i][j] = 0.0f;

    const float* xA = x + (size_t)row0 * (NB * D) + (size_t)n * D;
    const float* Wn = W0 + (size_t)n * D * E2;

    // A-load assignment: 128 threads cover 128 rows; 2 groups cover k-halves.
    const int mA  = tid & 127;
    const int kqA = (tid >> 7) * 8;            // 0 or 8
    // B-load assignment: 16 k-rows x (16 threads * 8 cols)
    const int krB = tid >> 4;
    const int c0B = (tid & 15) * 8;
    const int eB  = (c0B < 64) ? (ja + c0B) : (512 + ja + (c0B - 64));

    for (int k0 = 0; k0 < D; k0 += 16) {
        {
            const float* src = xA + (size_t)mA * (NB * D) + k0 + kqA;
            float4 a0 = *(const float4*)(src);
            float4 a1 = *(const float4*)(src + 4);
            As[kqA + 0][mA] = a0.x; As[kqA + 1][mA] = a0.y;
            As[kqA + 2][mA] = a0.z; As[kqA + 3][mA] = a0.w;
            As[kqA + 4][mA] = a1.x; As[kqA + 5][mA] = a1.y;
            As[kqA + 6][mA] = a1.z; As[kqA + 7][mA] = a1.w;
        }
        {
            const float* src = Wn + (size_t)(k0 + krB) * E2 + eB;
            *(float4*)&Bs[krB][c0B]     = *(const float4*)(src);
            *(float4*)&Bs[krB][c0B + 4] = *(const float4*)(src + 4);
        }
        __syncthreads();

        #pragma unroll
        for (int kk = 0; kk < 16; kk++) {
            float af[8], bf[8];
            *(float4*)&af[0] = *(const float4*)&As[kk][ty * 8];
            *(float4*)&af[4] = *(const float4*)&As[kk][ty * 8 + 4];
            *(float4*)&bf[0] = *(const float4*)&Bs[kk][tx * 4];        // a-cols
            *(float4*)&bf[4] = *(const float4*)&Bs[kk][64 + tx * 4];   // gate-cols
            #pragma unroll
            for (int i = 0; i < 8; i++)
                #pragma unroll
                for (int j = 0; j < 8; j++)
                    acc[i][j] = fmaf(af[i], bf[j], acc[i][j]);
        }
        __syncthreads();
    }

    // Epilogue: bias + GLU, write 8x4 h values per thread (float4 rows).
    float ba[4], bg[4];
    #pragma unroll
    for (int j = 0; j < 4; j++) {
        ba[j] = b0[n * E2 + ja + tx * 4 + j];
        bg[j] = b0[n * E2 + 512 + ja + tx * 4 + j];
    }
    #pragma unroll
    for (int i = 0; i < 8; i++) {
        const int row = row0 + ty * 8 + i;
        float v[4];
        #pragma unroll
        for (int j = 0; j < 4; j++)
            v[j] = glu(acc[i][j] + ba[j], acc[i][j + 4] + bg[j]);
        float4 hv = make_float4(v[0], v[1], v[2], v[3]);
        *(float4*)&g_h[((size_t)row * NB + n) * D + ja + tx * 4] = hv;
    }
}

// ---------------------------------------------------------------------------
// Stage 2: per band n (di = 8<<(n/4)): out_slice = GLU(h[:,n,:] @ W1_slice + b1_slice)
// Grid: (BT/128, 8 d-col tiles of 32, 24 bands); blocks beyond di exit early.
// Thread (tx,ty): 8 rows x 2 d-cols (each d-col = one a-col + one gate-col).
// ---------------------------------------------------------------------------
__global__ __launch_bounds__(256) void stage2_kernel(
    const float* __restrict__ W1, const float* __restrict__ b1,
    float* __restrict__ out)
{
    const int n   = blockIdx.z;
    const int gl  = n >> 2;
    const int di  = 8 << gl;
    const int jd0 = blockIdx.y * 32;
    if (jd0 >= di) return;

    const int on   = 32 * ((1 << gl) - 1) + (n & 3) * di;  // output col offset
    const int coff = 2 * on;                               // W1 col offset

    const int row0 = blockIdx.x * 128;

    __shared__ __align__(16) float Hs[16][128];   // Hs[k][m]
    __shared__ __align__(16) float Ws[16][64];    // [k][c]: c<32 a-cols, c>=32 gate

    const int tid = threadIdx.x;
    const int tx  = tid & 15;
    const int ty  = tid >> 4;

    float acc[8][4];
    #pragma unroll
    for (int i = 0; i < 8; i++)
        #pragma unroll
        for (int j = 0; j < 4; j++) acc[i][j] = 0.0f;

    const float* hA = g_h + (size_t)row0 * (NB * D) + (size_t)n * D;

    const int mA  = tid & 127;
    const int kqA = (tid >> 7) * 8;
    const int krW = tid >> 4;
    const int c0W = (tid & 15) * 4;
    bool wvalid; int ecol;
    if (c0W < 32) { wvalid = (jd0 + c0W) < di;        ecol = coff + jd0 + c0W; }
    else          { wvalid = (jd0 + (c0W - 32)) < di; ecol = coff + di + jd0 + (c0W - 32); }

    for (int k0 = 0; k0 < D; k0 += 16) {
        {
            const float* src = hA + (size_t)mA * (NB * D) + k0 + kqA;
            float4 a0 = *(const float4*)(src);
            float4 a1 = *(const float4*)(src + 4);
            Hs[kqA + 0][mA] = a0.x; Hs[kqA + 1][mA] = a0.y;
            Hs[kqA + 2][mA] = a0.z; Hs[kqA + 3][mA] = a0.w;
            Hs[kqA + 4][mA] = a1.x; Hs[kqA + 5][mA] = a1.y;
            Hs[kqA + 6][mA] = a1.z; Hs[kqA + 7][mA] = a1.w;
        }
        {
            float4 wv = make_float4(0.f, 0.f, 0.f, 0.f);
            if (wvalid)
                wv = *(const float4*)(W1 + (size_t)(k0 + krW) * W1C + ecol);
            *(float4*)&Ws[krW][c0W] = wv;
        }
        __syncthreads();

        #pragma unroll
        for (int kk = 0; kk < 16; kk++) {
            float af[8];
            *(float4*)&af[0] = *(const float4*)&Hs[kk][ty * 8];
            *(float4*)&af[4] = *(const float4*)&Hs[kk][ty * 8 + 4];
            float2 bv = *(const float2*)&Ws[kk][tx * 2];        // a cols
            float2 gv = *(const float2*)&Ws[kk][32 + tx * 2];   // gate cols
            #pragma unroll
            for (int i = 0; i < 8; i++) {
                acc[i][0] = fmaf(af[i], bv.x, acc[i][0]);
                acc[i][1] = fmaf(af[i], bv.y, acc[i][1]);
                acc[i][2] = fmaf(af[i], gv.x, acc[i][2]);
                acc[i][3] = fmaf(af[i], gv.y, acc[i][3]);
            }
        }
        __syncthreads();
    }

    const int jd = jd0 + tx * 2;
    if (jd >= di) return;   // whole pair invalid together (di multiple of 8)

    const float ba0 = b1[coff + jd],      ba1 = b1[coff + jd + 1];
    const float bg0 = b1[coff + di + jd], bg1 = b1[coff + di + jd + 1];

    #pragma unroll
    for (int i = 0; i < 8; i++) {
        const int row = row0 + ty * 8 + i;
        float2 ov;
        ov.x = glu(acc[i][0] + ba0, acc[i][2] + bg0);
        ov.y = glu(acc[i][1] + ba1, acc[i][3] + bg1);
        *(float2*)&out[(size_t)row * OUTW + on + jd] = ov;
    }
}

// ---------------------------------------------------------------------------
extern "C" void kernel_launch(void* const* d_in, const int* in_sizes, int n_in,
                              void* d_out, int out_size)
{
    const float* x  = (const float*)d_in[0];
    const float* W0 = (const float*)d_in[1];
    const float* b0 = (const float*)d_in[2];
    const float* W1 = (const float*)d_in[3];
    const float* b1 = (const float*)d_in[4];
    float* out = (float*)d_out;

    stage1_kernel<<<dim3(BT / 128, 8, NB), 256>>>(x, W0, b0);
    stage2_kernel<<<dim3(BT / 128, 8, NB), 256>>>(W1, b1, out);
}

// round 2
// speedup vs baseline: 1.0192x; 1.0192x over previous
#include <cuda_runtime.h>
#include <math.h>

// Problem constants
#define BT    2048      // B*T = 4*512
#define NB    24        // bands
#define D     512       // DIM
#define E2    1024      // 2*DIM
#define OUTW  2016      // sum(DIM_INPUTS)
#define W1C   4032      // 2*OUTW

// Scratch for stage-1 output h: [BT][NB][D] fp32 = 96 MB.
__device__ float g_h[(size_t)BT * NB * D];

typedef unsigned long long u64;

__device__ __forceinline__ u64 pack2(float lo, float hi) {
    u64 r; asm("mov.b64 %0, {%1, %2};" : "=l"(r) : "f"(lo), "f"(hi)); return r;
}
__device__ __forceinline__ void fma2(u64& c, u64 a, u64 b) {
    asm("fma.rn.f32x2 %0, %1, %2, %0;" : "+l"(c) : "l"(a), "l"(b));
}
__device__ __forceinline__ float2 unpack2(u64 v) {
    float2 f; asm("mov.b64 {%0, %1}, %2;" : "=f"(f.x), "=f"(f.y) : "l"(v)); return f;
}

__device__ __forceinline__ float fast_tanh(float x) {
    float r; asm("tanh.approx.f32 %0, %1;" : "=f"(r) : "f"(x)); return r;
}
__device__ __forceinline__ float glu(float a, float g) {
    return fast_tanh(a) * __fdividef(1.0f, 1.0f + __expf(-g));
}

// ---------------------------------------------------------------------------
// Stage 1: z = x[:, :, n, :] @ W0[n] + b0[n];  h = tanh(z_a) * sigmoid(z_g)
// Grid: (BT/128, 512/64 a-cols, 24 bands). Block 256 threads.
// Thread (tx,ty) in 16x16: 8 rows x (4 a-cols + 4 gate-cols), rows packed in
// pairs for fma.rn.f32x2 (accumulators are f32x2 in 64-bit regs).
// ---------------------------------------------------------------------------
__global__ __launch_bounds__(256, 2) void stage1_kernel(
    const float* __restrict__ x, const float* __restrict__ W0,
    const float* __restrict__ b0)
{
    const int row0 = blockIdx.x * 128;
    const int ja   = blockIdx.y * 64;
    const int n    = blockIdx.z;

    __shared__ __align__(16) float As[16][128];   // As[k][m]
    __shared__ __align__(16) float Bs[16][128];   // [k][c]: c<64 a-cols, c>=64 gate

    const int tid = threadIdx.x;
    const int tx  = tid & 15;
    const int ty  = tid >> 4;

    // acc[i2][j]: row-pair i2 (rows 2*i2, 2*i2+1 of this thread's 8),
    // cols j<4 = a-cols, j>=4 = gate-cols. Packed f32x2.
    u64 acc[4][8];
    #pragma unroll
    for (int i = 0; i < 4; i++)
        #pragma unroll
        for (int j = 0; j < 8; j++) acc[i][j] = 0ULL;

    const float* xA = x + (size_t)row0 * (NB * D) + (size_t)n * D;
    const float* Wn = W0 + (size_t)n * D * E2;

    const int mA  = tid & 127;
    const int kqA = (tid >> 7) * 8;            // 0 or 8
    const int krB = tid >> 4;
    const int c0B = (tid & 15) * 8;
    const int eB  = (c0B < 64) ? (ja + c0B) : (512 + ja + (c0B - 64));

    for (int k0 = 0; k0 < D; k0 += 16) {
        {
            const float* src = xA + (size_t)mA * (NB * D) + k0 + kqA;
            float4 a0 = *(const float4*)(src);
            float4 a1 = *(const float4*)(src + 4);
            As[kqA + 0][mA] = a0.x; As[kqA + 1][mA] = a0.y;
            As[kqA + 2][mA] = a0.z; As[kqA + 3][mA] = a0.w;
            As[kqA + 4][mA] = a1.x; As[kqA + 5][mA] = a1.y;
            As[kqA + 6][mA] = a1.z; As[kqA + 7][mA] = a1.w;
        }
        {
            const float* src = Wn + (size_t)(k0 + krB) * E2 + eB;
            *(float4*)&Bs[krB][c0B]     = *(const float4*)(src);
            *(float4*)&Bs[krB][c0B + 4] = *(const float4*)(src + 4);
        }
        __syncthreads();

        #pragma unroll
        for (int kk = 0; kk < 16; kk++) {
            // a: 8 consecutive rows = 4 packed pairs, loaded directly.
            ulonglong2 a01 = *(const ulonglong2*)&As[kk][ty * 8];
            ulonglong2 a23 = *(const ulonglong2*)&As[kk][ty * 8 + 4];
            u64 ap[4] = {a01.x, a01.y, a23.x, a23.y};

            float bf[8];
            *(float4*)&bf[0] = *(const float4*)&Bs[kk][tx * 4];        // a-cols
            *(float4*)&bf[4] = *(const float4*)&Bs[kk][64 + tx * 4];   // gate-cols
            u64 bd[8];
            #pragma unroll
            for (int j = 0; j < 8; j++) bd[j] = pack2(bf[j], bf[j]);

            #pragma unroll
            for (int i = 0; i < 4; i++)
                #pragma unroll
                for (int j = 0; j < 8; j++)
                    fma2(acc[i][j], ap[i], bd[j]);
        }
        __syncthreads();
    }

    // Epilogue: bias + GLU, 8 rows x 4 h values per thread.
    float ba[4], bg[4];
    #pragma unroll
    for (int j = 0; j < 4; j++) {
        ba[j] = b0[n * E2 + ja + tx * 4 + j];
        bg[j] = b0[n * E2 + 512 + ja + tx * 4 + j];
    }
    #pragma unroll
    for (int i2 = 0; i2 < 4; i2++) {
        float2 va[4], vg[4];
        #pragma unroll
        for (int j = 0; j < 4; j++) {
            va[j] = unpack2(acc[i2][j]);
            vg[j] = unpack2(acc[i2][j + 4]);
        }
        const int rlo = row0 + ty * 8 + i2 * 2;
        float4 h0, h1;
        h0.x = glu(va[0].x + ba[0], vg[0].x + bg[0]);
        h0.y = glu(va[1].x + ba[1], vg[1].x + bg[1]);
        h0.z = glu(va[2].x + ba[2], vg[2].x + bg[2]);
        h0.w = glu(va[3].x + ba[3], vg[3].x + bg[3]);
        h1.x = glu(va[0].y + ba[0], vg[0].y + bg[0]);
        h1.y = glu(va[1].y + ba[1], vg[1].y + bg[1]);
        h1.z = glu(va[2].y + ba[2], vg[2].y + bg[2]);
        h1.w = glu(va[3].y + ba[3], vg[3].y + bg[3]);
        *(float4*)&g_h[((size_t)rlo * NB + n) * D + ja + tx * 4]       = h0;
        *(float4*)&g_h[((size_t)(rlo + 1) * NB + n) * D + ja + tx * 4] = h1;
    }
}

// ---------------------------------------------------------------------------
// Stage 2: per band n (di = 8<<(n/4)): out_slice = GLU(h[:,n,:] @ W1_slice + b1)
// Grid: (BT/128, 8 d-col tiles of 32, 24 bands); blocks beyond di exit early.
// Thread (tx,ty): 8 rows (4 packed pairs) x 2 d-cols (= 2 a-cols + 2 gate-cols).
// ---------------------------------------------------------------------------
__global__ __launch_bounds__(256, 2) void stage2_kernel(
    const float* __restrict__ W1, const float* __restrict__ b1,
    float* __restrict__ out)
{
    const int n   = blockIdx.z;
    const int gl  = n >> 2;
    const int di  = 8 << gl;
    const int jd0 = blockIdx.y * 32;
    if (jd0 >= di) return;

    const int on   = 32 * ((1 << gl) - 1) + (n & 3) * di;  // output col offset
    const int coff = 2 * on;                               // W1 col offset

    const int row0 = blockIdx.x * 128;

    __shared__ __align__(16) float Hs[16][128];   // Hs[k][m]
    __shared__ __align__(16) float Ws[16][64];    // [k][c]: c<32 a, c>=32 gate

    const int tid = threadIdx.x;
    const int tx  = tid & 15;
    const int ty  = tid >> 4;

    u64 acc[4][4];   // [row-pair][j]: j<2 a-cols, j>=2 gate-cols
    #pragma unroll
    for (int i = 0; i < 4; i++)
        #pragma unroll
        for (int j = 0; j < 4; j++) acc[i][j] = 0ULL;

    const float* hA = g_h + (size_t)row0 * (NB * D) + (size_t)n * D;

    const int mA  = tid & 127;
    const int kqA = (tid >> 7) * 8;
    const int krW = tid >> 4;
    const int c0W = (tid & 15) * 4;
    bool wvalid; int ecol;
    if (c0W < 32) { wvalid = (jd0 + c0W) < di;        ecol = coff + jd0 + c0W; }
    else          { wvalid = (jd0 + (c0W - 32)) < di; ecol = coff + di + jd0 + (c0W - 32); }

    for (int k0 = 0; k0 < D; k0 += 16) {
        {
            const float* src = hA + (size_t)mA * (NB * D) + k0 + kqA;
            float4 a0 = *(const float4*)(src);
            float4 a1 = *(const float4*)(src + 4);
            Hs[kqA + 0][mA] = a0.x; Hs[kqA + 1][mA] = a0.y;
            Hs[kqA + 2][mA] = a0.z; Hs[kqA + 3][mA] = a0.w;
            Hs[kqA + 4][mA] = a1.x; Hs[kqA + 5][mA] = a1.y;
            Hs[kqA + 6][mA] = a1.z; Hs[kqA + 7][mA] = a1.w;
        }
        {
            float4 wv = make_float4(0.f, 0.f, 0.f, 0.f);
            if (wvalid)
                wv = *(const float4*)(W1 + (size_t)(k0 + krW) * W1C + ecol);
            *(float4*)&Ws[krW][c0W] = wv;
        }
        __syncthreads();

        #pragma unroll
        for (int kk = 0; kk < 16; kk++) {
            ulonglong2 a01 = *(const ulonglong2*)&Hs[kk][ty * 8];
            ulonglong2 a23 = *(const ulonglong2*)&Hs[kk][ty * 8 + 4];
            u64 ap[4] = {a01.x, a01.y, a23.x, a23.y};

            float2 bv = *(const float2*)&Ws[kk][tx * 2];        // a cols
            float2 gv = *(const float2*)&Ws[kk][32 + tx * 2];   // gate cols
            u64 bd[4] = {pack2(bv.x, bv.x), pack2(bv.y, bv.y),
                         pack2(gv.x, gv.x), pack2(gv.y, gv.y)};

            #pragma unroll
            for (int i = 0; i < 4; i++)
                #pragma unroll
                for (int j = 0; j < 4; j++)
                    fma2(acc[i][j], ap[i], bd[j]);
        }
        __syncthreads();
    }

    const int jd = jd0 + tx * 2;
    if (jd >= di) return;   // pair invalid together (di multiple of 8)

    const float ba0 = b1[coff + jd],      ba1 = b1[coff + jd + 1];
    const float bg0 = b1[coff + di + jd], bg1 = b1[coff + di + jd + 1];

    #pragma unroll
    for (int i2 = 0; i2 < 4; i2++) {
        float2 a0 = unpack2(acc[i2][0]);
        float2 a1 = unpack2(acc[i2][1]);
        float2 g0 = unpack2(acc[i2][2]);
        float2 g1 = unpack2(acc[i2][3]);
        const int rlo = row0 + ty * 8 + i2 * 2;
        float2 olo, ohi;
        olo.x = glu(a0.x + ba0, g0.x + bg0);
        olo.y = glu(a1.x + ba1, g1.x + bg1);
        ohi.x = glu(a0.y + ba0, g0.y + bg0);
        ohi.y = glu(a1.y + ba1, g1.y + bg1);
        *(float2*)&out[(size_t)rlo * OUTW + on + jd]       = olo;
        *(float2*)&out[(size_t)(rlo + 1) * OUTW + on + jd] = ohi;
    }
}

// ---------------------------------------------------------------------------
extern "C" void kernel_launch(void* const* d_in, const int* in_sizes, int n_in,
                              void* d_out, int out_size)
{
    const float* x  = (const float*)d_in[0];
    const float* W0 = (const float*)d_in[1];
    const float* b0 = (const float*)d_in[2];
    const float* W1 = (const float*)d_in[3];
    const float* b1 = (const float*)d_in[4];
    float* out = (float*)d_out;

    stage1_kernel<<<dim3(BT / 128, 8, NB), 256>>>(x, W0, b0);
    stage2_kernel<<<dim3(BT / 128, 8, NB), 256>>>(W1, b1, out);
}

// round 4
// speedup vs baseline: 1.6948x; 1.6628x over previous
#include <cuda_runtime.h>
#include <cuda_bf16.h>
#include <cstdint>

// ---------------------------------------------------------------------------
// Problem constants
// ---------------------------------------------------------------------------
#define BT    2048      // B*T
#define NB    24        // bands
#define D     512       // DIM
#define E2    1024      // 2*DIM
#define OUTW  2016      // sum(DIM_INPUTS)
#define W1C   4032      // 2*OUTW
#define LDS   40        // smem row stride in bf16 elements (32 data + 8 pad)

// Scratch globals (allocation-guard-safe)
__device__ __nv_bfloat16 g_xh[(size_t)BT * NB * D];   // x hi
__device__ __nv_bfloat16 g_xl[(size_t)BT * NB * D];   // x lo
__device__ __nv_bfloat16 g_wh[(size_t)NB * E2 * D];   // W0^T hi  [n][e][k]
__device__ __nv_bfloat16 g_wl[(size_t)NB * E2 * D];   // W0^T lo
__device__ __nv_bfloat16 g_hh[(size_t)BT * NB * D];   // h hi
__device__ __nv_bfloat16 g_hl[(size_t)BT * NB * D];   // h lo
__device__ __nv_bfloat16 g_vh[(size_t)W1C * D];       // W1^T hi  [e][k]
__device__ __nv_bfloat16 g_vl[(size_t)W1C * D];       // W1^T lo

// ---------------------------------------------------------------------------
// Helpers
// ---------------------------------------------------------------------------
__device__ __forceinline__ uint32_t smem_u32(const void* p) {
    uint32_t a;
    asm("{ .reg .u64 t; cvta.to.shared.u64 t, %1; cvt.u32.u64 %0, t; }"
        : "=r"(a) : "l"(p));
    return a;
}
__device__ __forceinline__ void ldm_x4(uint32_t* r, uint32_t addr) {
    asm volatile("ldmatrix.sync.aligned.m8n8.x4.shared.b16 {%0,%1,%2,%3}, [%4];"
        : "=r"(r[0]), "=r"(r[1]), "=r"(r[2]), "=r"(r[3]) : "r"(addr));
}
__device__ __forceinline__ void mma_bf16(float* c, const uint32_t* a,
                                         const uint32_t* b) {
    asm volatile(
        "mma.sync.aligned.m16n8k16.row.col.f32.bf16.bf16.f32 "
        "{%0,%1,%2,%3}, {%4,%5,%6,%7}, {%8,%9}, {%0,%1,%2,%3};"
        : "+f"(c[0]), "+f"(c[1]), "+f"(c[2]), "+f"(c[3])
        : "r"(a[0]), "r"(a[1]), "r"(a[2]), "r"(a[3]), "r"(b[0]), "r"(b[1]));
}
__device__ __forceinline__ float fast_tanh(float x) {
    float r; asm("tanh.approx.f32 %0, %1;" : "=f"(r) : "f"(x)); return r;
}
__device__ __forceinline__ float glu(float a, float g) {
    return fast_tanh(a) * __fdividef(1.0f, 1.0f + __expf(-g));
}
__device__ __forceinline__ uint32_t bfpack(float x, float y) {
    __nv_bfloat162 t = __floats2bfloat162_rn(x, y);
    return *(uint32_t*)&t;
}
__device__ __forceinline__ uint32_t pack_bf2(__nv_bfloat16 lo, __nv_bfloat16 hi) {
    return ((uint32_t)__bfloat16_as_ushort(hi) << 16) | __bfloat16_as_ushort(lo);
}

// ---------------------------------------------------------------------------
// Prologue 1: split x (f32) into hi/lo bf16, same layout.
// ---------------------------------------------------------------------------
__global__ __launch_bounds__(256) void cvt_x_kernel(const float* __restrict__ x)
{
    const size_t total4 = (size_t)BT * NB * D / 4;
    uint2* outh = (uint2*)g_xh;
    uint2* outl = (uint2*)g_xl;
    const float4* in = (const float4*)x;
    for (size_t i = blockIdx.x * blockDim.x + threadIdx.x; i < total4;
         i += (size_t)gridDim.x * blockDim.x) {
        float4 v = in[i];
        __nv_bfloat16 h0 = __float2bfloat16_rn(v.x), h1 = __float2bfloat16_rn(v.y);
        __nv_bfloat16 h2 = __float2bfloat16_rn(v.z), h3 = __float2bfloat16_rn(v.w);
        __nv_bfloat16 l0 = __float2bfloat16_rn(v.x - __bfloat162float(h0));
        __nv_bfloat16 l1 = __float2bfloat16_rn(v.y - __bfloat162float(h1));
        __nv_bfloat16 l2 = __float2bfloat16_rn(v.z - __bfloat162float(h2));
        __nv_bfloat16 l3 = __float2bfloat16_rn(v.w - __bfloat162float(h3));
        outh[i] = make_uint2(pack_bf2(h0, h1), pack_bf2(h2, h3));
        outl[i] = make_uint2(pack_bf2(l0, l1), pack_bf2(l2, l3));
    }
}

// ---------------------------------------------------------------------------
// Prologue 2: W0 [n][k][e] f32 -> g_wh/g_wl [n][e][k] bf16 (transpose+split)
// ---------------------------------------------------------------------------
__global__ __launch_bounds__(256) void cvt_w0_kernel(const float* __restrict__ W0)
{
    __shared__ float t[32][33];
    const int k0 = blockIdx.x * 32;
    const int e0 = blockIdx.y * 32;
    const int n  = blockIdx.z;
    const int tx = threadIdx.x, ty = threadIdx.y;

    #pragma unroll
    for (int i = 0; i < 32; i += 8)
        t[ty + i][tx] = W0[((size_t)n * D + k0 + ty + i) * E2 + e0 + tx];
    __syncthreads();
    #pragma unroll
    for (int i = 0; i < 32; i += 8) {
        float v = t[tx][ty + i];
        __nv_bfloat16 h = __float2bfloat16_rn(v);
        __nv_bfloat16 l = __float2bfloat16_rn(v - __bfloat162float(h));
        size_t idx = ((size_t)n * E2 + e0 + ty + i) * D + k0 + tx;
        g_wh[idx] = h;
        g_wl[idx] = l;
    }
}

// ---------------------------------------------------------------------------
// Prologue 3: W1 [k][e] f32 (D x W1C) -> g_vh/g_vl [e][k] bf16
// ---------------------------------------------------------------------------
__global__ __launch_bounds__(256) void cvt_w1_kernel(const float* __restrict__ W1)
{
    __shared__ float t[32][33];
    const int k0 = blockIdx.x * 32;
    const int e0 = blockIdx.y * 32;
    const int tx = threadIdx.x, ty = threadIdx.y;

    #pragma unroll
    for (int i = 0; i < 32; i += 8)
        t[ty + i][tx] = W1[(size_t)(k0 + ty + i) * W1C + e0 + tx];
    __syncthreads();
    #pragma unroll
    for (int i = 0; i < 32; i += 8) {
        float v = t[tx][ty + i];
        __nv_bfloat16 h = __float2bfloat16_rn(v);
        __nv_bfloat16 l = __float2bfloat16_rn(v - __bfloat162float(h));
        size_t idx = (size_t)(e0 + ty + i) * D + k0 + tx;
        g_vh[idx] = h;
        g_vl[idx] = l;
    }
}

// ---------------------------------------------------------------------------
// Stage 1 (warp MMA): z = x @ W0[n] + b0[n]; h = GLU(z) -> g_hh/g_hl
// Grid: (16, 8, 24). Block 256 (8 warps: 4 m x 2 n).
// CTA tile: M=128, N=128 (tile cols 0-63 = a-cols ja.., 64-127 = gate-cols).
// Warp tile: 32 x 64 (a-cols warp_n*32.. + their gates at +64, so GLU pairs
// are within-thread). K chunked at 32, bf16 hi/lo 3-product split.
// ---------------------------------------------------------------------------
__global__ __launch_bounds__(256) void stage1_mma_kernel(
    const float* __restrict__ b0)
{
    __shared__ __nv_bfloat16 Ah[128 * LDS], Al[128 * LDS];
    __shared__ __nv_bfloat16 Bh[128 * LDS], Bl[128 * LDS];

    const int tid = threadIdx.x;
    const int wid = tid >> 5;
    const int lane = tid & 31;
    const int warp_m = wid & 3;
    const int warp_n = wid >> 2;
    const int row0 = blockIdx.x * 128;
    const int ja   = blockIdx.y * 64;
    const int n    = blockIdx.z;

    float acc[2][8][4];
    #pragma unroll
    for (int mi = 0; mi < 2; mi++)
        #pragma unroll
        for (int j = 0; j < 8; j++)
            #pragma unroll
            for (int r = 0; r < 4; r++) acc[mi][j][r] = 0.0f;

    const uint32_t sAh = smem_u32(Ah), sAl = smem_u32(Al);
    const uint32_t sBh = smem_u32(Bh), sBl = smem_u32(Bl);

    // ldmatrix per-thread address components
    const int aRow = warp_m * 32 + (lane & 15);
    const int aK   = (lane >> 4) * 8;
    const int bN   = (lane & 7) + ((lane >> 4) << 3);
    const int bK   = ((lane >> 3) & 1) << 3;

    // global load assignments (vec8 of bf16 = 16B)
    const int lr  = tid >> 2;          // row/col 0..127 (with it*64 offset? no: see below)
    const int lsg = (tid & 3) * 8;     // k segment

    for (int chunk = 0; chunk < 16; chunk++) {
        const int k0 = chunk * 32;

        // ---- A: 128 rows x 32 k, hi+lo ----
        #pragma unroll
        for (int it = 0; it < 2; it++) {
            const int r = lr + it * 64;
            const size_t src = ((size_t)(row0 + r) * NB + n) * D + k0 + lsg;
            *(uint4*)&Ah[r * LDS + lsg] = *(const uint4*)(g_xh + src);
            *(uint4*)&Al[r * LDS + lsg] = *(const uint4*)(g_xl + src);
        }
        // ---- B: 128 cols x 32 k, hi+lo ----
        #pragma unroll
        for (int it = 0; it < 2; it++) {
            const int c = lr + it * 64;
            const int e = (c < 64) ? (ja + c) : (512 + ja + (c - 64));
            const size_t src = ((size_t)n * E2 + e) * D + k0 + lsg;
            *(uint4*)&Bh[c * LDS + lsg] = *(const uint4*)(g_wh + src);
            *(uint4*)&Bl[c * LDS + lsg] = *(const uint4*)(g_wl + src);
        }
        __syncthreads();

        #pragma unroll
        for (int ks = 0; ks < 2; ks++) {
            uint32_t ah[2][4], al[2][4];
            #pragma unroll
            for (int mi = 0; mi < 2; mi++) {
                const uint32_t off =
                    (uint32_t)(((aRow + mi * 16) * LDS + ks * 16 + aK) * 2);
                ldm_x4(ah[mi], sAh + off);
                ldm_x4(al[mi], sAl + off);
            }
            #pragma unroll
            for (int idx = 0; idx < 4; idx++) {
                const int bc = (idx < 2) ? (warp_n * 32 + idx * 16)
                                         : (64 + warp_n * 32 + (idx - 2) * 16);
                const uint32_t off =
                    (uint32_t)(((bc + bN) * LDS + ks * 16 + bK) * 2);
                uint32_t bh[4], bl[4];
                ldm_x4(bh, sBh + off);
                ldm_x4(bl, sBl + off);
                #pragma unroll
                for (int s = 0; s < 2; s++) {
                    const int j = idx * 2 + s;
                    #pragma unroll
                    for (int mi = 0; mi < 2; mi++) {
                        mma_bf16(acc[mi][j], ah[mi], &bh[2 * s]);
                        mma_bf16(acc[mi][j], ah[mi], &bl[2 * s]);
                        mma_bf16(acc[mi][j], al[mi], &bh[2 * s]);
                    }
                }
            }
        }
        __syncthreads();
    }

    // ---- Epilogue: bias + GLU, write h as bf16 hi/lo ----
    const int g   = lane >> 2;
    const int tig = lane & 3;

    #pragma unroll
    for (int mi = 0; mi < 2; mi++) {
        #pragma unroll
        for (int j = 0; j < 4; j++) {
            const int colL = warp_n * 32 + j * 8 + 2 * tig;   // 0..63
            const int col  = ja + colL;
            const float ba0 = b0[n * E2 + col];
            const float ba1 = b0[n * E2 + col + 1];
            const float bg0 = b0[n * E2 + 512 + col];
            const float bg1 = b0[n * E2 + 512 + col + 1];
            #pragma unroll
            for (int half = 0; half < 2; half++) {
                const int row = row0 + warp_m * 32 + mi * 16 + g + half * 8;
                const float a0 = acc[mi][j][half * 2 + 0] + ba0;
                const float a1 = acc[mi][j][half * 2 + 1] + ba1;
                const float q0 = acc[mi][j + 4][half * 2 + 0] + bg0;
                const float q1 = acc[mi][j + 4][half * 2 + 1] + bg1;
                const float h0 = glu(a0, q0);
                const float h1 = glu(a1, q1);
                __nv_bfloat16 hh0 = __float2bfloat16_rn(h0);
                __nv_bfloat16 hh1 = __float2bfloat16_rn(h1);
                float hl0 = h0 - __bfloat162float(hh0);
                float hl1 = h1 - __bfloat162float(hh1);
                const size_t o = ((size_t)row * NB + n) * D + col;
                *(uint32_t*)(g_hh + o) = pack_bf2(hh0, hh1);
                *(uint32_t*)(g_hl + o) =
                    pack_bf2(__float2bfloat16_rn(hl0), __float2bfloat16_rn(hl1));
            }
        }
    }
}

// ---------------------------------------------------------------------------
// Stage 2 (warp MMA): out_slice = GLU(h[:,n,:] @ W1_slice + b1_slice)
// Grid: (16, 8, 24), blocks past di exit. Block 256 (8 warps: 4 m x 2 n).
// CTA tile: M=128, GEMM N=64 (tile cols 0-31 = a-cols jd0.., 32-63 = gates).
// Warp tile: 32 x 32 (16 a + 16 matching gate cols).
// ---------------------------------------------------------------------------
__global__ __launch_bounds__(256) void stage2_mma_kernel(
    const float* __restrict__ b1, float* __restrict__ out)
{
    const int n   = blockIdx.z;
    const int gl  = n >> 2;
    const int di  = 8 << gl;
    const int jd0 = blockIdx.y * 32;
    if (jd0 >= di) return;

    const int on   = 32 * ((1 << gl) - 1) + (n & 3) * di;
    const int coff = 2 * on;
    const int row0 = blockIdx.x * 128;

    __shared__ __nv_bfloat16 Ah[128 * LDS], Al[128 * LDS];
    __shared__ __nv_bfloat16 Bh[64 * LDS], Bl[64 * LDS];

    const int tid = threadIdx.x;
    const int wid = tid >> 5;
    const int lane = tid & 31;
    const int warp_m = wid & 3;
    const int warp_n = wid >> 2;

    float acc[2][4][4];
    #pragma unroll
    for (int mi = 0; mi < 2; mi++)
        #pragma unroll
        for (int j = 0; j < 4; j++)
            #pragma unroll
            for (int r = 0; r < 4; r++) acc[mi][j][r] = 0.0f;

    const uint32_t sAh = smem_u32(Ah), sAl = smem_u32(Al);
    const uint32_t sBh = smem_u32(Bh), sBl = smem_u32(Bl);

    const int aRow = warp_m * 32 + (lane & 15);
    const int aK   = (lane >> 4) * 8;
    const int bN   = (lane & 7) + ((lane >> 4) << 3);
    const int bK   = ((lane >> 3) & 1) << 3;

    const int lr  = tid >> 2;
    const int lsg = (tid & 3) * 8;

    // B column -> W1 column mapping (precomputed, chunk-invariant)
    const int cB    = lr;                       // 0..63 (single it for B)
    const int jdB   = jd0 + (cB & 31);
    const bool valB = jdB < di;
    const int eB    = (cB < 32) ? (coff + jdB) : (coff + di + jdB);

    for (int chunk = 0; chunk < 16; chunk++) {
        const int k0 = chunk * 32;

        #pragma unroll
        for (int it = 0; it < 2; it++) {
            const int r = lr + it * 64;
            const size_t src = ((size_t)(row0 + r) * NB + n) * D + k0 + lsg;
            *(uint4*)&Ah[r * LDS + lsg] = *(const uint4*)(g_hh + src);
            *(uint4*)&Al[r * LDS + lsg] = *(const uint4*)(g_hl + src);
        }
        {
            uint4 vh = make_uint4(0, 0, 0, 0), vl = make_uint4(0, 0, 0, 0);
            if (valB) {
                const size_t src = (size_t)eB * D + k0 + lsg;
                vh = *(const uint4*)(g_vh + src);
                vl = *(const uint4*)(g_vl + src);
            }
            *(uint4*)&Bh[cB * LDS + lsg] = vh;
            *(uint4*)&Bl[cB * LDS + lsg] = vl;
        }
        __syncthreads();

        #pragma unroll
        for (int ks = 0; ks < 2; ks++) {
            uint32_t ah[2][4], al[2][4];
            #pragma unroll
            for (int mi = 0; mi < 2; mi++) {
                const uint32_t off =
                    (uint32_t)(((aRow + mi * 16) * LDS + ks * 16 + aK) * 2);
                ldm_x4(ah[mi], sAh + off);
                ldm_x4(al[mi], sAl + off);
            }
            #pragma unroll
            for (int idx = 0; idx < 2; idx++) {
                const int bc = (idx == 0) ? (warp_n * 16) : (32 + warp_n * 16);
                const uint32_t off =
                    (uint32_t)(((bc + bN) * LDS + ks * 16 + bK) * 2);
                uint32_t bh[4], bl[4];
                ldm_x4(bh, sBh + off);
                ldm_x4(bl, sBl + off);
                #pragma unroll
                for (int s = 0; s < 2; s++) {
                    const int j = idx * 2 + s;
                    #pragma unroll
                    for (int mi = 0; mi < 2; mi++) {
                        mma_bf16(acc[mi][j], ah[mi], &bh[2 * s]);
                        mma_bf16(acc[mi][j], ah[mi], &bl[2 * s]);
                        mma_bf16(acc[mi][j], al[mi], &bh[2 * s]);
                    }
                }
            }
        }
        __syncthreads();
    }

    // ---- Epilogue: bias + GLU -> out ----
    const int g   = lane >> 2;
    const int tig = lane & 3;

    #pragma unroll
    for (int mi = 0; mi < 2; mi++) {
        #pragma unroll
        for (int j = 0; j < 2; j++) {
            const int jd = jd0 + warp_n * 16 + j * 8 + 2 * tig;
            if (jd >= di) continue;
            const float ba0 = b1[coff + jd];
            const float ba1 = b1[coff + jd + 1];
            const float bg0 = b1[coff + di + jd];
            const float bg1 = b1[coff + di + jd + 1];
            #pragma unroll
            for (int half = 0; half < 2; half++) {
                const int row = row0 + warp_m * 32 + mi * 16 + g + half * 8;
                const float a0 = acc[mi][j][half * 2 + 0] + ba0;
                const float a1 = acc[mi][j][half * 2 + 1] + ba1;
                const float q0 = acc[mi][j + 2][half * 2 + 0] + bg0;
                const float q1 = acc[mi][j + 2][half * 2 + 1] + bg1;
                float2 ov;
                ov.x = glu(a0, q0);
                ov.y = glu(a1, q1);
                *(float2*)&out[(size_t)row * OUTW + on + jd] = ov;
            }
        }
    }
}

// ---------------------------------------------------------------------------
extern "C" void kernel_launch(void* const* d_in, const int* in_sizes, int n_in,
                              void* d_out, int out_size)
{
    const float* x  = (const float*)d_in[0];
    const float* W0 = (const float*)d_in[1];
    const float* b0 = (const float*)d_in[2];
    const float* W1 = (const float*)d_in[3];
    const float* b1 = (const float*)d_in[4];
    float* out = (float*)d_out;

    cvt_x_kernel<<<4096, 256>>>(x);
    cvt_w0_kernel<<<dim3(D / 32, E2 / 32, NB), dim3(32, 8)>>>(W0);
    cvt_w1_kernel<<<dim3(D / 32, W1C / 32, 1), dim3(32, 8)>>>(W1);
    stage1_mma_kernel<<<dim3(BT / 128, 8, NB), 256>>>(b0);
    stage2_mma_kernel<<<dim3(BT / 128, 8, NB), 256>>>(b1, out);
}

// round 5
// speedup vs baseline: 2.3534x; 1.3886x over previous
#include <cuda_runtime.h>
#include <cuda_bf16.h>
#include <cstdint>

// ---------------------------------------------------------------------------
// Problem constants
// ---------------------------------------------------------------------------
#define BT    2048      // B*T
#define NB    24        // bands
#define D     512       // DIM
#define E2    1024      // 2*DIM
#define OUTW  2016      // sum(DIM_INPUTS)
#define W1C   4032      // 2*OUTW
#define LDSE  40        // smem row stride in bf16 elements (32 data + 8 pad)

// Scratch globals
__device__ __nv_bfloat16 g_xh[(size_t)BT * NB * D];   // x hi
__device__ __nv_bfloat16 g_xl[(size_t)BT * NB * D];   // x lo
__device__ __nv_bfloat16 g_wh[(size_t)NB * E2 * D];   // W0^T hi  [n][e][k]
__device__ __nv_bfloat16 g_wl[(size_t)NB * E2 * D];   // W0^T lo
__device__ __nv_bfloat16 g_hh[(size_t)BT * NB * D];   // h hi
__device__ __nv_bfloat16 g_hl[(size_t)BT * NB * D];   // h lo
__device__ __nv_bfloat16 g_vh[(size_t)W1C * D];       // W1^T hi  [e][k]
__device__ __nv_bfloat16 g_vl[(size_t)W1C * D];       // W1^T lo

// ---------------------------------------------------------------------------
// Helpers
// ---------------------------------------------------------------------------
__device__ __forceinline__ uint32_t smem_u32(const void* p) {
    uint32_t a;
    asm("{ .reg .u64 t; cvta.to.shared.u64 t, %1; cvt.u32.u64 %0, t; }"
        : "=r"(a) : "l"(p));
    return a;
}
__device__ __forceinline__ void cp16(uint32_t dst, const void* src) {
    asm volatile("cp.async.cg.shared.global [%0], [%1], 16;"
                 :: "r"(dst), "l"(src));
}
__device__ __forceinline__ void cp16z(uint32_t dst, const void* src, bool valid) {
    int sz = valid ? 16 : 0;
    asm volatile("cp.async.cg.shared.global [%0], [%1], 16, %2;"
                 :: "r"(dst), "l"(src), "r"(sz));
}
__device__ __forceinline__ void cp_commit() {
    asm volatile("cp.async.commit_group;");
}
__device__ __forceinline__ void cp_wait1() {
    asm volatile("cp.async.wait_group 1;");
}
__device__ __forceinline__ void cp_wait0() {
    asm volatile("cp.async.wait_group 0;");
}
__device__ __forceinline__ void ldm_x4(uint32_t* r, uint32_t addr) {
    asm volatile("ldmatrix.sync.aligned.m8n8.x4.shared.b16 {%0,%1,%2,%3}, [%4];"
        : "=r"(r[0]), "=r"(r[1]), "=r"(r[2]), "=r"(r[3]) : "r"(addr));
}
__device__ __forceinline__ void mma_bf16(float* c, const uint32_t* a,
                                         const uint32_t* b) {
    asm volatile(
        "mma.sync.aligned.m16n8k16.row.col.f32.bf16.bf16.f32 "
        "{%0,%1,%2,%3}, {%4,%5,%6,%7}, {%8,%9}, {%0,%1,%2,%3};"
        : "+f"(c[0]), "+f"(c[1]), "+f"(c[2]), "+f"(c[3])
        : "r"(a[0]), "r"(a[1]), "r"(a[2]), "r"(a[3]), "r"(b[0]), "r"(b[1]));
}
__device__ __forceinline__ float fast_tanh(float x) {
    float r; asm("tanh.approx.f32 %0, %1;" : "=f"(r) : "f"(x)); return r;
}
__device__ __forceinline__ float glu(float a, float g) {
    return fast_tanh(a) * __fdividef(1.0f, 1.0f + __expf(-g));
}
__device__ __forceinline__ uint32_t pack_bf2(__nv_bfloat16 lo, __nv_bfloat16 hi) {
    return ((uint32_t)__bfloat16_as_ushort(hi) << 16) | __bfloat16_as_ushort(lo);
}

// ---------------------------------------------------------------------------
// Prologues (unchanged from R4)
// ---------------------------------------------------------------------------
__global__ __launch_bounds__(256) void cvt_x_kernel(const float* __restrict__ x)
{
    const size_t total4 = (size_t)BT * NB * D / 4;
    uint2* outh = (uint2*)g_xh;
    uint2* outl = (uint2*)g_xl;
    const float4* in = (const float4*)x;
    for (size_t i = blockIdx.x * blockDim.x + threadIdx.x; i < total4;
         i += (size_t)gridDim.x * blockDim.x) {
        float4 v = in[i];
        __nv_bfloat16 h0 = __float2bfloat16_rn(v.x), h1 = __float2bfloat16_rn(v.y);
        __nv_bfloat16 h2 = __float2bfloat16_rn(v.z), h3 = __float2bfloat16_rn(v.w);
        __nv_bfloat16 l0 = __float2bfloat16_rn(v.x - __bfloat162float(h0));
        __nv_bfloat16 l1 = __float2bfloat16_rn(v.y - __bfloat162float(h1));
        __nv_bfloat16 l2 = __float2bfloat16_rn(v.z - __bfloat162float(h2));
        __nv_bfloat16 l3 = __float2bfloat16_rn(v.w - __bfloat162float(h3));
        outh[i] = make_uint2(pack_bf2(h0, h1), pack_bf2(h2, h3));
        outl[i] = make_uint2(pack_bf2(l0, l1), pack_bf2(l2, l3));
    }
}

__global__ __launch_bounds__(256) void cvt_w0_kernel(const float* __restrict__ W0)
{
    __shared__ float t[32][33];
    const int k0 = blockIdx.x * 32;
    const int e0 = blockIdx.y * 32;
    const int n  = blockIdx.z;
    const int tx = threadIdx.x, ty = threadIdx.y;

    #pragma unroll
    for (int i = 0; i < 32; i += 8)
        t[ty + i][tx] = W0[((size_t)n * D + k0 + ty + i) * E2 + e0 + tx];
    __syncthreads();
    #pragma unroll
    for (int i = 0; i < 32; i += 8) {
        float v = t[tx][ty + i];
        __nv_bfloat16 h = __float2bfloat16_rn(v);
        __nv_bfloat16 l = __float2bfloat16_rn(v - __bfloat162float(h));
        size_t idx = ((size_t)n * E2 + e0 + ty + i) * D + k0 + tx;
        g_wh[idx] = h;
        g_wl[idx] = l;
    }
}

__global__ __launch_bounds__(256) void cvt_w1_kernel(const float* __restrict__ W1)
{
    __shared__ float t[32][33];
    const int k0 = blockIdx.x * 32;
    const int e0 = blockIdx.y * 32;
    const int tx = threadIdx.x, ty = threadIdx.y;

    #pragma unroll
    for (int i = 0; i < 32; i += 8)
        t[ty + i][tx] = W1[(size_t)(k0 + ty + i) * W1C + e0 + tx];
    __syncthreads();
    #pragma unroll
    for (int i = 0; i < 32; i += 8) {
        float v = t[tx][ty + i];
        __nv_bfloat16 h = __float2bfloat16_rn(v);
        __nv_bfloat16 l = __float2bfloat16_rn(v - __bfloat162float(h));
        size_t idx = (size_t)(e0 + ty + i) * D + k0 + tx;
        g_vh[idx] = h;
        g_vl[idx] = l;
    }
}

// ---------------------------------------------------------------------------
// Stage 1 (warp MMA + cp.async double buffering)
// Grid: (16, 8, 24). Block 256 (8 warps: 4 m x 2 n).
// Dynamic smem: 2 buffers x [Ah|Al|Bh|Bl], each 128 x LDSE bf16 = 81920 B.
// ---------------------------------------------------------------------------
#define S1_MAT   (128 * LDSE)            // elems per matrix
#define S1_BUF   (4 * S1_MAT)            // elems per buffer
#define S1_SMEM  (2 * S1_BUF * 2)        // bytes total = 81920

__global__ __launch_bounds__(256) void stage1_mma_kernel(
    const float* __restrict__ b0)
{
    extern __shared__ __nv_bfloat16 smem[];

    const int tid = threadIdx.x;
    const int wid = tid >> 5;
    const int lane = tid & 31;
    const int warp_m = wid & 3;
    const int warp_n = wid >> 2;
    const int row0 = blockIdx.x * 128;
    const int ja   = blockIdx.y * 64;
    const int n    = blockIdx.z;

    float acc[2][8][4];
    #pragma unroll
    for (int mi = 0; mi < 2; mi++)
        #pragma unroll
        for (int j = 0; j < 8; j++)
            #pragma unroll
            for (int r = 0; r < 4; r++) acc[mi][j][r] = 0.0f;

    const uint32_t smb = smem_u32(smem);

    const int aRow = warp_m * 32 + (lane & 15);
    const int aK   = (lane >> 4) * 8;
    const int bN   = (lane & 7) + ((lane >> 4) << 3);
    const int bK   = ((lane >> 3) & 1) << 3;

    const int lr  = tid >> 2;          // 0..63
    const int lsg = (tid & 3) * 8;     // k segment (bf16 elems)

    // ---- async load of one K-chunk into buffer `buf` ----
    auto issue = [&](int chunk, int buf) {
        const int k0 = chunk * 32;
        const uint32_t base = smb + (uint32_t)(buf * S1_BUF) * 2;
        #pragma unroll
        for (int it = 0; it < 2; it++) {
            const int r = lr + it * 64;
            const size_t src = ((size_t)(row0 + r) * NB + n) * D + k0 + lsg;
            const uint32_t d = base + (uint32_t)(r * LDSE + lsg) * 2;
            cp16(d,                 g_xh + src);
            cp16(d + S1_MAT * 2,    g_xl + src);
        }
        #pragma unroll
        for (int it = 0; it < 2; it++) {
            const int c = lr + it * 64;
            const int e = (c < 64) ? (ja + c) : (512 + ja + (c - 64));
            const size_t src = ((size_t)n * E2 + e) * D + k0 + lsg;
            const uint32_t d = base + (uint32_t)(c * LDSE + lsg) * 2;
            cp16(d + 2 * S1_MAT * 2, g_wh + src);
            cp16(d + 3 * S1_MAT * 2, g_wl + src);
        }
        cp_commit();
    };

    issue(0, 0);

    for (int chunk = 0; chunk < 16; chunk++) {
        if (chunk + 1 < 16) { issue(chunk + 1, (chunk + 1) & 1); cp_wait1(); }
        else                { cp_wait0(); }
        __syncthreads();

        const uint32_t base = smb + (uint32_t)((chunk & 1) * S1_BUF) * 2;
        const uint32_t sAh = base;
        const uint32_t sAl = base + S1_MAT * 2;
        const uint32_t sBh = base + 2 * S1_MAT * 2;
        const uint32_t sBl = base + 3 * S1_MAT * 2;

        #pragma unroll
        for (int ks = 0; ks < 2; ks++) {
            uint32_t ah[2][4], al[2][4];
            #pragma unroll
            for (int mi = 0; mi < 2; mi++) {
                const uint32_t off =
                    (uint32_t)(((aRow + mi * 16) * LDSE + ks * 16 + aK) * 2);
                ldm_x4(ah[mi], sAh + off);
                ldm_x4(al[mi], sAl + off);
            }
            #pragma unroll
            for (int idx = 0; idx < 4; idx++) {
                const int bc = (idx < 2) ? (warp_n * 32 + idx * 16)
                                         : (64 + warp_n * 32 + (idx - 2) * 16);
                const uint32_t off =
                    (uint32_t)(((bc + bN) * LDSE + ks * 16 + bK) * 2);
                uint32_t bh[4], bl[4];
                ldm_x4(bh, sBh + off);
                ldm_x4(bl, sBl + off);
                #pragma unroll
                for (int s = 0; s < 2; s++) {
                    const int j = idx * 2 + s;
                    #pragma unroll
                    for (int mi = 0; mi < 2; mi++) {
                        mma_bf16(acc[mi][j], ah[mi], &bh[2 * s]);
                        mma_bf16(acc[mi][j], ah[mi], &bl[2 * s]);
                        mma_bf16(acc[mi][j], al[mi], &bh[2 * s]);
                    }
                }
            }
        }
        __syncthreads();
    }

    // ---- Epilogue: bias + GLU, write h as bf16 hi/lo ----
    const int g   = lane >> 2;
    const int tig = lane & 3;

    #pragma unroll
    for (int mi = 0; mi < 2; mi++) {
        #pragma unroll
        for (int j = 0; j < 4; j++) {
            const int col = ja + warp_n * 32 + j * 8 + 2 * tig;
            const float ba0 = b0[n * E2 + col];
            const float ba1 = b0[n * E2 + col + 1];
            const float bg0 = b0[n * E2 + 512 + col];
            const float bg1 = b0[n * E2 + 512 + col + 1];
            #pragma unroll
            for (int half = 0; half < 2; half++) {
                const int row = row0 + warp_m * 32 + mi * 16 + g + half * 8;
                const float a0 = acc[mi][j][half * 2 + 0] + ba0;
                const float a1 = acc[mi][j][half * 2 + 1] + ba1;
                const float q0 = acc[mi][j + 4][half * 2 + 0] + bg0;
                const float q1 = acc[mi][j + 4][half * 2 + 1] + bg1;
                const float h0 = glu(a0, q0);
                const float h1 = glu(a1, q1);
                __nv_bfloat16 hh0 = __float2bfloat16_rn(h0);
                __nv_bfloat16 hh1 = __float2bfloat16_rn(h1);
                float hl0 = h0 - __bfloat162float(hh0);
                float hl1 = h1 - __bfloat162float(hh1);
                const size_t o = ((size_t)row * NB + n) * D + col;
                *(uint32_t*)(g_hh + o) = pack_bf2(hh0, hh1);
                *(uint32_t*)(g_hl + o) =
                    pack_bf2(__float2bfloat16_rn(hl0), __float2bfloat16_rn(hl1));
            }
        }
    }
}

// ---------------------------------------------------------------------------
// Stage 2 (warp MMA + cp.async double buffering)
// Dynamic smem: 2 x [Ah(128) | Al(128) | Bh(64) | Bl(64)] x LDSE = 61440 B.
// ---------------------------------------------------------------------------
#define S2_AMAT  (128 * LDSE)
#define S2_BMAT  (64 * LDSE)
#define S2_BUF   (2 * S2_AMAT + 2 * S2_BMAT)
#define S2_SMEM  (2 * S2_BUF * 2)

__global__ __launch_bounds__(256) void stage2_mma_kernel(
    const float* __restrict__ b1, float* __restrict__ out)
{
    const int n   = blockIdx.z;
    const int gl  = n >> 2;
    const int di  = 8 << gl;
    const int jd0 = blockIdx.y * 32;
    if (jd0 >= di) return;

    const int on   = 32 * ((1 << gl) - 1) + (n & 3) * di;
    const int coff = 2 * on;
    const int row0 = blockIdx.x * 128;

    extern __shared__ __nv_bfloat16 smem[];

    const int tid = threadIdx.x;
    const int wid = tid >> 5;
    const int lane = tid & 31;
    const int warp_m = wid & 3;
    const int warp_n = wid >> 2;

    float acc[2][4][4];
    #pragma unroll
    for (int mi = 0; mi < 2; mi++)
        #pragma unroll
        for (int j = 0; j < 4; j++)
            #pragma unroll
            for (int r = 0; r < 4; r++) acc[mi][j][r] = 0.0f;

    const uint32_t smb = smem_u32(smem);

    const int aRow = warp_m * 32 + (lane & 15);
    const int aK   = (lane >> 4) * 8;
    const int bN   = (lane & 7) + ((lane >> 4) << 3);
    const int bK   = ((lane >> 3) & 1) << 3;

    const int lr  = tid >> 2;
    const int lsg = (tid & 3) * 8;

    const int cB    = lr;                       // 0..63
    const int jdB   = jd0 + (cB & 31);
    const bool valB = jdB < di;
    const int eB    = (cB < 32) ? (coff + jdB) : (coff + di + jdB);

    auto issue = [&](int chunk, int buf) {
        const int k0 = chunk * 32;
        const uint32_t base = smb + (uint32_t)(buf * S2_BUF) * 2;
        #pragma unroll
        for (int it = 0; it < 2; it++) {
            const int r = lr + it * 64;
            const size_t src = ((size_t)(row0 + r) * NB + n) * D + k0 + lsg;
            const uint32_t d = base + (uint32_t)(r * LDSE + lsg) * 2;
            cp16(d,                g_hh + src);
            cp16(d + S2_AMAT * 2,  g_hl + src);
        }
        {
            const size_t src = (size_t)eB * D + k0 + lsg;
            const uint32_t d = base + (uint32_t)(2 * S2_AMAT + cB * LDSE + lsg) * 2;
            cp16z(d,               g_vh + src, valB);
            cp16z(d + S2_BMAT * 2, g_vl + src, valB);
        }
        cp_commit();
    };

    issue(0, 0);

    for (int chunk = 0; chunk < 16; chunk++) {
        if (chunk + 1 < 16) { issue(chunk + 1, (chunk + 1) & 1); cp_wait1(); }
        else                { cp_wait0(); }
        __syncthreads();

        const uint32_t base = smb + (uint32_t)((chunk & 1) * S2_BUF) * 2;
        const uint32_t sAh = base;
        const uint32_t sAl = base + S2_AMAT * 2;
        const uint32_t sBh = base + 2 * S2_AMAT * 2;
        const uint32_t sBl = base + (2 * S2_AMAT + S2_BMAT) * 2;

        #pragma unroll
        for (int ks = 0; ks < 2; ks++) {
            uint32_t ah[2][4], al[2][4];
            #pragma unroll
            for (int mi = 0; mi < 2; mi++) {
                const uint32_t off =
                    (uint32_t)(((aRow + mi * 16) * LDSE + ks * 16 + aK) * 2);
                ldm_x4(ah[mi], sAh + off);
                ldm_x4(al[mi], sAl + off);
            }
            #pragma unroll
            for (int idx = 0; idx < 2; idx++) {
                const int bc = (idx == 0) ? (warp_n * 16) : (32 + warp_n * 16);
                const uint32_t off =
                    (uint32_t)(((bc + bN) * LDSE + ks * 16 + bK) * 2);
                uint32_t bh[4], bl[4];
                ldm_x4(bh, sBh + off);
                ldm_x4(bl, sBl + off);
                #pragma unroll
                for (int s = 0; s < 2; s++) {
                    const int j = idx * 2 + s;
                    #pragma unroll
                    for (int mi = 0; mi < 2; mi++) {
                        mma_bf16(acc[mi][j], ah[mi], &bh[2 * s]);
                        mma_bf16(acc[mi][j], ah[mi], &bl[2 * s]);
                        mma_bf16(acc[mi][j], al[mi], &bh[2 * s]);
                    }
                }
            }
        }
        __syncthreads();
    }

    // ---- Epilogue ----
    const int g   = lane >> 2;
    const int tig = lane & 3;

    #pragma unroll
    for (int mi = 0; mi < 2; mi++) {
        #pragma unroll
        for (int j = 0; j < 2; j++) {
            const int jd = jd0 + warp_n * 16 + j * 8 + 2 * tig;
            if (jd >= di) continue;
            const float ba0 = b1[coff + jd];
            const float ba1 = b1[coff + jd + 1];
            const float bg0 = b1[coff + di + jd];
            const float bg1 = b1[coff + di + jd + 1];
            #pragma unroll
            for (int half = 0; half < 2; half++) {
                const int row = row0 + warp_m * 32 + mi * 16 + g + half * 8;
                const float a0 = acc[mi][j][half * 2 + 0] + ba0;
                const float a1 = acc[mi][j][half * 2 + 1] + ba1;
                const float q0 = acc[mi][j + 2][half * 2 + 0] + bg0;
                const float q1 = acc[mi][j + 2][half * 2 + 1] + bg1;
                float2 ov;
                ov.x = glu(a0, q0);
                ov.y = glu(a1, q1);
                *(float2*)&out[(size_t)row * OUTW + on + jd] = ov;
            }
        }
    }
}

// ---------------------------------------------------------------------------
extern "C" void kernel_launch(void* const* d_in, const int* in_sizes, int n_in,
                              void* d_out, int out_size)
{
    const float* x  = (const float*)d_in[0];
    const float* W0 = (const float*)d_in[1];
    const float* b0 = (const float*)d_in[2];
    const float* W1 = (const float*)d_in[3];
    const float* b1 = (const float*)d_in[4];
    float* out = (float*)d_out;

    cudaFuncSetAttribute(stage1_mma_kernel,
                         cudaFuncAttributeMaxDynamicSharedMemorySize, S1_SMEM);
    cudaFuncSetAttribute(stage2_mma_kernel,
                         cudaFuncAttributeMaxDynamicSharedMemorySize, S2_SMEM);

    cvt_x_kernel<<<4096, 256>>>(x);
    cvt_w0_kernel<<<dim3(D / 32, E2 / 32, NB), dim3(32, 8)>>>(W0);
    cvt_w1_kernel<<<dim3(D / 32, W1C / 32, 1), dim3(32, 8)>>>(W1);
    stage1_mma_kernel<<<dim3(BT / 128, 8, NB), 256, S1_SMEM>>>(b0);
    stage2_mma_kernel<<<dim3(BT / 128, 8, NB), 256, S2_SMEM>>>(b1, out);
}

// round 6
// speedup vs baseline: 2.3536x; 1.0001x over previous
#include <cuda_runtime.h>
#include <cuda_bf16.h>
#include <cstdint>

// ---------------------------------------------------------------------------
// Problem constants
// ---------------------------------------------------------------------------
#define BT    2048      // B*T
#define NB    24        // bands
#define D     512       // DIM
#define E2    1024      // 2*DIM
#define OUTW  2016      // sum(DIM_INPUTS)
#define W1C   4032      // 2*OUTW
#define LDSE  40        // smem row stride in bf16 elements (32 data + 8 pad)

// Scratch globals
__device__ __nv_bfloat16 g_xh[(size_t)BT * NB * D];   // x hi
__device__ __nv_bfloat16 g_xl[(size_t)BT * NB * D];   // x lo
__device__ __nv_bfloat16 g_wh[(size_t)NB * E2 * D];   // W0^T hi  [n][e][k]
__device__ __nv_bfloat16 g_wl[(size_t)NB * E2 * D];   // W0^T lo
__device__ __nv_bfloat16 g_hh[(size_t)BT * NB * D];   // h hi
__device__ __nv_bfloat16 g_hl[(size_t)BT * NB * D];   // h lo
__device__ __nv_bfloat16 g_vh[(size_t)W1C * D];       // W1^T hi  [e][k]
__device__ __nv_bfloat16 g_vl[(size_t)W1C * D];       // W1^T lo

// ---------------------------------------------------------------------------
// Helpers
// ---------------------------------------------------------------------------
__device__ __forceinline__ uint32_t smem_u32(const void* p) {
    uint32_t a;
    asm("{ .reg .u64 t; cvta.to.shared.u64 t, %1; cvt.u32.u64 %0, t; }"
        : "=r"(a) : "l"(p));
    return a;
}
__device__ __forceinline__ void cp16(uint32_t dst, const void* src) {
    asm volatile("cp.async.cg.shared.global [%0], [%1], 16;"
                 :: "r"(dst), "l"(src));
}
__device__ __forceinline__ void cp16z(uint32_t dst, const void* src, bool valid) {
    int sz = valid ? 16 : 0;
    asm volatile("cp.async.cg.shared.global [%0], [%1], 16, %2;"
                 :: "r"(dst), "l"(src), "r"(sz));
}
__device__ __forceinline__ void cp_commit() {
    asm volatile("cp.async.commit_group;");
}
__device__ __forceinline__ void cp_wait1() {
    asm volatile("cp.async.wait_group 1;");
}
__device__ __forceinline__ void cp_wait0() {
    asm volatile("cp.async.wait_group 0;");
}
__device__ __forceinline__ void ldm_x4(uint32_t* r, uint32_t addr) {
    asm volatile("ldmatrix.sync.aligned.m8n8.x4.shared.b16 {%0,%1,%2,%3}, [%4];"
        : "=r"(r[0]), "=r"(r[1]), "=r"(r[2]), "=r"(r[3]) : "r"(addr));
}
__device__ __forceinline__ void mma_bf16(float* c, const uint32_t* a,
                                         const uint32_t* b) {
    asm volatile(
        "mma.sync.aligned.m16n8k16.row.col.f32.bf16.bf16.f32 "
        "{%0,%1,%2,%3}, {%4,%5,%6,%7}, {%8,%9}, {%0,%1,%2,%3};"
        : "+f"(c[0]), "+f"(c[1]), "+f"(c[2]), "+f"(c[3])
        : "r"(a[0]), "r"(a[1]), "r"(a[2]), "r"(a[3]), "r"(b[0]), "r"(b[1]));
}
__device__ __forceinline__ float fast_tanh(float x) {
    float r; asm("tanh.approx.f32 %0, %1;" : "=f"(r) : "f"(x)); return r;
}
__device__ __forceinline__ float glu(float a, float g) {
    return fast_tanh(a) * __fdividef(1.0f, 1.0f + __expf(-g));
}
__device__ __forceinline__ uint32_t pack_bf2(__nv_bfloat16 lo, __nv_bfloat16 hi) {
    return ((uint32_t)__bfloat16_as_ushort(hi) << 16) | __bfloat16_as_ushort(lo);
}

// ---------------------------------------------------------------------------
// Prologues (unchanged)
// ---------------------------------------------------------------------------
__global__ __launch_bounds__(256) void cvt_x_kernel(const float* __restrict__ x)
{
    const size_t total4 = (size_t)BT * NB * D / 4;
    uint2* outh = (uint2*)g_xh;
    uint2* outl = (uint2*)g_xl;
    const float4* in = (const float4*)x;
    for (size_t i = blockIdx.x * blockDim.x + threadIdx.x; i < total4;
         i += (size_t)gridDim.x * blockDim.x) {
        float4 v = in[i];
        __nv_bfloat16 h0 = __float2bfloat16_rn(v.x), h1 = __float2bfloat16_rn(v.y);
        __nv_bfloat16 h2 = __float2bfloat16_rn(v.z), h3 = __float2bfloat16_rn(v.w);
        __nv_bfloat16 l0 = __float2bfloat16_rn(v.x - __bfloat162float(h0));
        __nv_bfloat16 l1 = __float2bfloat16_rn(v.y - __bfloat162float(h1));
        __nv_bfloat16 l2 = __float2bfloat16_rn(v.z - __bfloat162float(h2));
        __nv_bfloat16 l3 = __float2bfloat16_rn(v.w - __bfloat162float(h3));
        outh[i] = make_uint2(pack_bf2(h0, h1), pack_bf2(h2, h3));
        outl[i] = make_uint2(pack_bf2(l0, l1), pack_bf2(l2, l3));
    }
}

__global__ __launch_bounds__(256) void cvt_w0_kernel(const float* __restrict__ W0)
{
    __shared__ float t[32][33];
    const int k0 = blockIdx.x * 32;
    const int e0 = blockIdx.y * 32;
    const int n  = blockIdx.z;
    const int tx = threadIdx.x, ty = threadIdx.y;

    #pragma unroll
    for (int i = 0; i < 32; i += 8)
        t[ty + i][tx] = W0[((size_t)n * D + k0 + ty + i) * E2 + e0 + tx];
    __syncthreads();
    #pragma unroll
    for (int i = 0; i < 32; i += 8) {
        float v = t[tx][ty + i];
        __nv_bfloat16 h = __float2bfloat16_rn(v);
        __nv_bfloat16 l = __float2bfloat16_rn(v - __bfloat162float(h));
        size_t idx = ((size_t)n * E2 + e0 + ty + i) * D + k0 + tx;
        g_wh[idx] = h;
        g_wl[idx] = l;
    }
}

__global__ __launch_bounds__(256) void cvt_w1_kernel(const float* __restrict__ W1)
{
    __shared__ float t[32][33];
    const int k0 = blockIdx.x * 32;
    const int e0 = blockIdx.y * 32;
    const int tx = threadIdx.x, ty = threadIdx.y;

    #pragma unroll
    for (int i = 0; i < 32; i += 8)
        t[ty + i][tx] = W1[(size_t)(k0 + ty + i) * W1C + e0 + tx];
    __syncthreads();
    #pragma unroll
    for (int i = 0; i < 32; i += 8) {
        float v = t[tx][ty + i];
        __nv_bfloat16 h = __float2bfloat16_rn(v);
        __nv_bfloat16 l = __float2bfloat16_rn(v - __bfloat162float(h));
        size_t idx = (size_t)(e0 + ty + i) * D + k0 + tx;
        g_vh[idx] = h;
        g_vl[idx] = l;
    }
}

// ---------------------------------------------------------------------------
// Stage 1 (warp MMA + cp.async double buffering + product-sweep ordering)
// ---------------------------------------------------------------------------
#define S1_MAT   (128 * LDSE)            // elems per matrix
#define S1_BUF   (4 * S1_MAT)            // elems per buffer
#define S1_SMEM  (2 * S1_BUF * 2)        // bytes total = 81920

__global__ __launch_bounds__(256) void stage1_mma_kernel(
    const float* __restrict__ b0)
{
    extern __shared__ __nv_bfloat16 smem[];

    const int tid = threadIdx.x;
    const int wid = tid >> 5;
    const int lane = tid & 31;
    const int warp_m = wid & 3;
    const int warp_n = wid >> 2;
    const int row0 = blockIdx.x * 128;
    const int ja   = blockIdx.y * 64;
    const int n    = blockIdx.z;

    float acc[2][8][4];
    #pragma unroll
    for (int mi = 0; mi < 2; mi++)
        #pragma unroll
        for (int j = 0; j < 8; j++)
            #pragma unroll
            for (int r = 0; r < 4; r++) acc[mi][j][r] = 0.0f;

    const uint32_t smb = smem_u32(smem);

    const int aRow = warp_m * 32 + (lane & 15);
    const int aK   = (lane >> 4) * 8;
    const int bN   = (lane & 7) + ((lane >> 4) << 3);
    const int bK   = ((lane >> 3) & 1) << 3;

    const int lr  = tid >> 2;          // 0..63
    const int lsg = (tid & 3) * 8;     // k segment (bf16 elems)

    auto issue = [&](int chunk, int buf) {
        const int k0 = chunk * 32;
        const uint32_t base = smb + (uint32_t)(buf * S1_BUF) * 2;
        #pragma unroll
        for (int it = 0; it < 2; it++) {
            const int r = lr + it * 64;
            const size_t src = ((size_t)(row0 + r) * NB + n) * D + k0 + lsg;
            const uint32_t d = base + (uint32_t)(r * LDSE + lsg) * 2;
            cp16(d,                 g_xh + src);
            cp16(d + S1_MAT * 2,    g_xl + src);
        }
        #pragma unroll
        for (int it = 0; it < 2; it++) {
            const int c = lr + it * 64;
            const int e = (c < 64) ? (ja + c) : (512 + ja + (c - 64));
            const size_t src = ((size_t)n * E2 + e) * D + k0 + lsg;
            const uint32_t d = base + (uint32_t)(c * LDSE + lsg) * 2;
            cp16(d + 2 * S1_MAT * 2, g_wh + src);
            cp16(d + 3 * S1_MAT * 2, g_wl + src);
        }
        cp_commit();
    };

    issue(0, 0);

    for (int chunk = 0; chunk < 16; chunk++) {
        if (chunk + 1 < 16) { issue(chunk + 1, (chunk + 1) & 1); cp_wait1(); }
        else                { cp_wait0(); }
        __syncthreads();

        const uint32_t base = smb + (uint32_t)((chunk & 1) * S1_BUF) * 2;
        const uint32_t sAh = base;
        const uint32_t sAl = base + S1_MAT * 2;
        const uint32_t sBh = base + 2 * S1_MAT * 2;
        const uint32_t sBl = base + 3 * S1_MAT * 2;

        #pragma unroll
        for (int ks = 0; ks < 2; ks++) {
            uint32_t ah[2][4], al[2][4];
            #pragma unroll
            for (int mi = 0; mi < 2; mi++) {
                const uint32_t off =
                    (uint32_t)(((aRow + mi * 16) * LDSE + ks * 16 + aK) * 2);
                ldm_x4(ah[mi], sAh + off);
                ldm_x4(al[mi], sAl + off);
            }
            #pragma unroll
            for (int idx = 0; idx < 4; idx++) {
                const int bc = (idx < 2) ? (warp_n * 32 + idx * 16)
                                         : (64 + warp_n * 32 + (idx - 2) * 16);
                const uint32_t off =
                    (uint32_t)(((bc + bN) * LDSE + ks * 16 + bK) * 2);
                uint32_t bh[4], bl[4];
                ldm_x4(bh, sBh + off);
                ldm_x4(bl, sBl + off);
                // Product sweeps: 4 independent accumulators per sweep;
                // RAW distance to same acc = 4 MMAs (was 1).
                #pragma unroll
                for (int s = 0; s < 2; s++)
                    #pragma unroll
                    for (int mi = 0; mi < 2; mi++)
                        mma_bf16(acc[mi][idx * 2 + s], ah[mi], &bh[2 * s]);
                #pragma unroll
                for (int s = 0; s < 2; s++)
                    #pragma unroll
                    for (int mi = 0; mi < 2; mi++)
                        mma_bf16(acc[mi][idx * 2 + s], ah[mi], &bl[2 * s]);
                #pragma unroll
                for (int s = 0; s < 2; s++)
                    #pragma unroll
                    for (int mi = 0; mi < 2; mi++)
                        mma_bf16(acc[mi][idx * 2 + s], al[mi], &bh[2 * s]);
            }
        }
        __syncthreads();
    }

    // ---- Epilogue: bias + GLU, write h as bf16 hi/lo ----
    const int g   = lane >> 2;
    const int tig = lane & 3;

    #pragma unroll
    for (int mi = 0; mi < 2; mi++) {
        #pragma unroll
        for (int j = 0; j < 4; j++) {
            const int col = ja + warp_n * 32 + j * 8 + 2 * tig;
            const float ba0 = b0[n * E2 + col];
            const float ba1 = b0[n * E2 + col + 1];
            const float bg0 = b0[n * E2 + 512 + col];
            const float bg1 = b0[n * E2 + 512 + col + 1];
            #pragma unroll
            for (int half = 0; half < 2; half++) {
                const int row = row0 + warp_m * 32 + mi * 16 + g + half * 8;
                const float a0 = acc[mi][j][half * 2 + 0] + ba0;
                const float a1 = acc[mi][j][half * 2 + 1] + ba1;
                const float q0 = acc[mi][j + 4][half * 2 + 0] + bg0;
                const float q1 = acc[mi][j + 4][half * 2 + 1] + bg1;
                const float h0 = glu(a0, q0);
                const float h1 = glu(a1, q1);
                __nv_bfloat16 hh0 = __float2bfloat16_rn(h0);
                __nv_bfloat16 hh1 = __float2bfloat16_rn(h1);
                float hl0 = h0 - __bfloat162float(hh0);
                float hl1 = h1 - __bfloat162float(hh1);
                const size_t o = ((size_t)row * NB + n) * D + col;
                *(uint32_t*)(g_hh + o) = pack_bf2(hh0, hh1);
                *(uint32_t*)(g_hl + o) =
                    pack_bf2(__float2bfloat16_rn(hl0), __float2bfloat16_rn(hl1));
            }
        }
    }
}

// ---------------------------------------------------------------------------
// Stage 2 (warp MMA + cp.async double buffering + product-sweep ordering)
// ---------------------------------------------------------------------------
#define S2_AMAT  (128 * LDSE)
#define S2_BMAT  (64 * LDSE)
#define S2_BUF   (2 * S2_AMAT + 2 * S2_BMAT)
#define S2_SMEM  (2 * S2_BUF * 2)

__global__ __launch_bounds__(256) void stage2_mma_kernel(
    const float* __restrict__ b1, float* __restrict__ out)
{
    const int n   = blockIdx.z;
    const int gl  = n >> 2;
    const int di  = 8 << gl;
    const int jd0 = blockIdx.y * 32;
    if (jd0 >= di) return;

    const int on   = 32 * ((1 << gl) - 1) + (n & 3) * di;
    const int coff = 2 * on;
    const int row0 = blockIdx.x * 128;

    extern __shared__ __nv_bfloat16 smem[];

    const int tid = threadIdx.x;
    const int wid = tid >> 5;
    const int lane = tid & 31;
    const int warp_m = wid & 3;
    const int warp_n = wid >> 2;

    float acc[2][4][4];
    #pragma unroll
    for (int mi = 0; mi < 2; mi++)
        #pragma unroll
        for (int j = 0; j < 4; j++)
            #pragma unroll
            for (int r = 0; r < 4; r++) acc[mi][j][r] = 0.0f;

    const uint32_t smb = smem_u32(smem);

    const int aRow = warp_m * 32 + (lane & 15);
    const int aK   = (lane >> 4) * 8;
    const int bN   = (lane & 7) + ((lane >> 4) << 3);
    const int bK   = ((lane >> 3) & 1) << 3;

    const int lr  = tid >> 2;
    const int lsg = (tid & 3) * 8;

    const int cB    = lr;                       // 0..63
    const int jdB   = jd0 + (cB & 31);
    const bool valB = jdB < di;
    const int eB    = (cB < 32) ? (coff + jdB) : (coff + di + jdB);

    auto issue = [&](int chunk, int buf) {
        const int k0 = chunk * 32;
        const uint32_t base = smb + (uint32_t)(buf * S2_BUF) * 2;
        #pragma unroll
        for (int it = 0; it < 2; it++) {
            const int r = lr + it * 64;
            const size_t src = ((size_t)(row0 + r) * NB + n) * D + k0 + lsg;
            const uint32_t d = base + (uint32_t)(r * LDSE + lsg) * 2;
            cp16(d,                g_hh + src);
            cp16(d + S2_AMAT * 2,  g_hl + src);
        }
        {
            const size_t src = (size_t)eB * D + k0 + lsg;
            const uint32_t d = base + (uint32_t)(2 * S2_AMAT + cB * LDSE + lsg) * 2;
            cp16z(d,               g_vh + src, valB);
            cp16z(d + S2_BMAT * 2, g_vl + src, valB);
        }
        cp_commit();
    };

    issue(0, 0);

    for (int chunk = 0; chunk < 16; chunk++) {
        if (chunk + 1 < 16) { issue(chunk + 1, (chunk + 1) & 1); cp_wait1(); }
        else                { cp_wait0(); }
        __syncthreads();

        const uint32_t base = smb + (uint32_t)((chunk & 1) * S2_BUF) * 2;
        const uint32_t sAh = base;
        const uint32_t sAl = base + S2_AMAT * 2;
        const uint32_t sBh = base + 2 * S2_AMAT * 2;
        const uint32_t sBl = base + (2 * S2_AMAT + S2_BMAT) * 2;

        #pragma unroll
        for (int ks = 0; ks < 2; ks++) {
            uint32_t ah[2][4], al[2][4];
            #pragma unroll
            for (int mi = 0; mi < 2; mi++) {
                const uint32_t off =
                    (uint32_t)(((aRow + mi * 16) * LDSE + ks * 16 + aK) * 2);
                ldm_x4(ah[mi], sAh + off);
                ldm_x4(al[mi], sAl + off);
            }
            #pragma unroll
            for (int idx = 0; idx < 2; idx++) {
                const int bc = (idx == 0) ? (warp_n * 16) : (32 + warp_n * 16);
                const uint32_t off =
                    (uint32_t)(((bc + bN) * LDSE + ks * 16 + bK) * 2);
                uint32_t bh[4], bl[4];
                ldm_x4(bh, sBh + off);
                ldm_x4(bl, sBl + off);
                #pragma unroll
                for (int s = 0; s < 2; s++)
                    #pragma unroll
                    for (int mi = 0; mi < 2; mi++)
                        mma_bf16(acc[mi][idx * 2 + s], ah[mi], &bh[2 * s]);
                #pragma unroll
                for (int s = 0; s < 2; s++)
                    #pragma unroll
                    for (int mi = 0; mi < 2; mi++)
                        mma_bf16(acc[mi][idx * 2 + s], ah[mi], &bl[2 * s]);
                #pragma unroll
                for (int s = 0; s < 2; s++)
                    #pragma unroll
                    for (int mi = 0; mi < 2; mi++)
                        mma_bf16(acc[mi][idx * 2 + s], al[mi], &bh[2 * s]);
            }
        }
        __syncthreads();
    }

    // ---- Epilogue ----
    const int g   = lane >> 2;
    const int tig = lane & 3;

    #pragma unroll
    for (int mi = 0; mi < 2; mi++) {
        #pragma unroll
        for (int j = 0; j < 2; j++) {
            const int jd = jd0 + warp_n * 16 + j * 8 + 2 * tig;
            if (jd >= di) continue;
            const float ba0 = b1[coff + jd];
            const float ba1 = b1[coff + jd + 1];
            const float bg0 = b1[coff + di + jd];
            const float bg1 = b1[coff + di + jd + 1];
            #pragma unroll
            for (int half = 0; half < 2; half++) {
                const int row = row0 + warp_m * 32 + mi * 16 + g + half * 8;
                const float a0 = acc[mi][j][half * 2 + 0] + ba0;
                const float a1 = acc[mi][j][half * 2 + 1] + ba1;
                const float q0 = acc[mi][j + 2][half * 2 + 0] + bg0;
                const float q1 = acc[mi][j + 2][half * 2 + 1] + bg1;
                float2 ov;
                ov.x = glu(a0, q0);
                ov.y = glu(a1, q1);
                *(float2*)&out[(size_t)row * OUTW + on + jd] = ov;
            }
        }
    }
}

// ---------------------------------------------------------------------------
extern "C" void kernel_launch(void* const* d_in, const int* in_sizes, int n_in,
                              void* d_out, int out_size)
{
    const float* x  = (const float*)d_in[0];
    const float* W0 = (const float*)d_in[1];
    const float* b0 = (const float*)d_in[2];
    const float* W1 = (const float*)d_in[3];
    const float* b1 = (const float*)d_in[4];
    float* out = (float*)d_out;

    cudaFuncSetAttribute(stage1_mma_kernel,
                         cudaFuncAttributeMaxDynamicSharedMemorySize, S1_SMEM);
    cudaFuncSetAttribute(stage2_mma_kernel,
                         cudaFuncAttributeMaxDynamicSharedMemorySize, S2_SMEM);

    cvt_x_kernel<<<4096, 256>>>(x);
    cvt_w0_kernel<<<dim3(D / 32, E2 / 32, NB), dim3(32, 8)>>>(W0);
    cvt_w1_kernel<<<dim3(D / 32, W1C / 32, 1), dim3(32, 8)>>>(W1);
    stage1_mma_kernel<<<dim3(BT / 128, 8, NB), 256, S1_SMEM>>>(b0);
    stage2_mma_kernel<<<dim3(BT / 128, 8, NB), 256, S2_SMEM>>>(b1, out);
}